// round 1
// baseline (speedup 1.0000x reference)
#include <cuda_runtime.h>
#include <cstdint>

// QSVT pointwise evaluation, reduced to SO(3) Bloch dynamics.
//
//  x = clamp(x,-1,1); s = sqrt(1-x^2)
//  r0 = (sin x, 0, cos x)
//  apply: Rz(2*phi_0), then 7x [ Refl(s,0,x), Rz(2*phi_j) ] with the final
//  Rz(2*phi_7) and RZ(theta) dropped (unit-modulus diagonal phases do not
//  change |v0|,|v1| and hence not <Z>).
//  Refl on (rx,rz): [[A,B],[B,-A]] with A = 1-2x^2, B = 2sx ; ry -> -ry.
//  ry sign-flips are folded into S~_k = (-1)^k sin(2 phi_k); we track
//  w = sigma*ry so reflections leave w untouched.
//  Output = rz.

typedef unsigned long long u64;

#define NROT 7

__device__ float g_c[NROT];   // cos(2 phi_k)
__device__ float g_sp[NROT];  // (+) (-1)^k sin(2 phi_k)
__device__ float g_sn[NROT];  // (-) (-1)^k sin(2 phi_k)

__global__ void qsvt_setup(const float* __restrict__ phi) {
    int k = threadIdx.x;
    if (k < NROT) {
        float s, c;
        sincosf(2.0f * phi[k], &s, &c);
        float sgn = (k & 1) ? -1.0f : 1.0f;
        g_c[k]  = c;
        g_sp[k] = sgn * s;
        g_sn[k] = -sgn * s;
    }
}

// ---- packed f32x2 helpers (Blackwell 2x fp32 path) ----
__device__ __forceinline__ u64 pk2(float lo, float hi) {
    u64 r; asm("mov.b64 %0, {%1, %2};" : "=l"(r) : "f"(lo), "f"(hi)); return r;
}
__device__ __forceinline__ void unpk2(u64 v, float& lo, float& hi) {
    asm("mov.b64 {%0, %1}, %2;" : "=f"(lo), "=f"(hi) : "l"(v));
}
__device__ __forceinline__ u64 fma2(u64 a, u64 b, u64 c) {
    u64 d; asm("fma.rn.f32x2 %0, %1, %2, %3;" : "=l"(d) : "l"(a), "l"(b), "l"(c)); return d;
}
__device__ __forceinline__ u64 mul2(u64 a, u64 b) {
    u64 d; asm("mul.rn.f32x2 %0, %1, %2;" : "=l"(d) : "l"(a), "l"(b)); return d;
}
__device__ __forceinline__ u64 add2(u64 a, u64 b) {
    u64 d; asm("add.rn.f32x2 %0, %1, %2;" : "=l"(d) : "l"(a), "l"(b)); return d;
}
// ---- scalar MUFU approximations (separate pipe from FMA) ----
__device__ __forceinline__ float aprx_sqrt(float x) {
    float r; asm("sqrt.approx.f32 %0, %1;" : "=f"(r) : "f"(x)); return r;
}
__device__ __forceinline__ float aprx_sin(float x) {
    float r; asm("sin.approx.f32 %0, %1;" : "=f"(r) : "f"(x)); return r;
}
__device__ __forceinline__ float aprx_cos(float x) {
    float r; asm("cos.approx.f32 %0, %1;" : "=f"(r) : "f"(x)); return r;
}

// Evaluate QSVT <Z> for two elements packed in f32x2. Returns packed rz.
__device__ __forceinline__ u64 qsvt_pair(float xa, float xb,
                                         const u64* __restrict__ C,
                                         const u64* __restrict__ SP,
                                         const u64* __restrict__ SN,
                                         u64 ONE, u64 NEG2) {
    // clamp + per-lane transcendentals (MUFU pipe)
    xa = fminf(fmaxf(xa, -1.0f), 1.0f);
    xb = fminf(fmaxf(xb, -1.0f), 1.0f);
    float ua = fmaxf(fmaf(-xa, xa, 1.0f), 0.0f);
    float ub = fmaxf(fmaf(-xb, xb, 1.0f), 0.0f);
    float sa = aprx_sqrt(ua);
    float sb = aprx_sqrt(ub);
    float sina = aprx_sin(xa), cosa = aprx_cos(xa);
    float sinb = aprx_sin(xb), cosb = aprx_cos(xb);

    u64 X   = pk2(xa, xb);
    u64 S   = pk2(sa, sb);
    u64 SIN = pk2(sina, sinb);

    u64 XX = mul2(X, X);
    u64 A  = fma2(XX, NEG2, ONE);           // 1 - 2x^2
    u64 An = A ^ 0x8000000080000000ULL;     // -(1 - 2x^2)  (ALU pipe)
    u64 Bv = mul2(add2(X, X), S);           // 2 s x

    // Rz(2*phi_0) applied to (sin x, 0):
    u64 rx = mul2(C[0], SIN);
    u64 w  = mul2(SN[0], SIN);
    u64 rz = pk2(cosa, cosb);

#pragma unroll
    for (int j = 1; j <= 7; j++) {
        // reflection about (s,0,x): rx' = A rx + B rz ; rz' = B rx - A rz
        u64 t1  = mul2(Bv, rz);
        u64 nrx = fma2(A, rx, t1);
        u64 t2  = mul2(An, rz);
        rz = fma2(Bv, rx, t2);
        rx = nrx;
        if (j < 7) {
            // Rz(2*phi_j) with sign-folded constants:
            // rx' = C rx + S~ w ; w' = C w - S~ rx
            u64 t3   = mul2(C[j], rx);
            u64 nrx2 = fma2(SP[j], w, t3);
            u64 t4   = mul2(C[j], w);
            w  = fma2(SN[j], rx, t4);
            rx = nrx2;
        }
    }
    return rz;  // <Z>
}

__global__ void __launch_bounds__(256) qsvt_main(const float* __restrict__ xin,
                                                 float* __restrict__ out,
                                                 int n) {
    // load rotation constants once per thread, duplicate-pack into f32x2
    u64 C[NROT], SP[NROT], SN[NROT];
#pragma unroll
    for (int k = 0; k < NROT; k++) {
        float cc = g_c[k], pp = g_sp[k], nn = g_sn[k];
        C[k]  = pk2(cc, cc);
        SP[k] = pk2(pp, pp);
        SN[k] = pk2(nn, nn);
    }
    const u64 ONE  = pk2(1.0f, 1.0f);
    const u64 NEG2 = pk2(-2.0f, -2.0f);

    long long tid  = (long long)blockIdx.x * blockDim.x + threadIdx.x;
    long long base = tid * 8;
    if (base >= n) return;

    if (base + 8 <= n) {
        float4 a = *reinterpret_cast<const float4*>(xin + base);
        float4 b = *reinterpret_cast<const float4*>(xin + base + 4);

        u64 r01 = qsvt_pair(a.x, a.y, C, SP, SN, ONE, NEG2);
        u64 r23 = qsvt_pair(a.z, a.w, C, SP, SN, ONE, NEG2);
        u64 r45 = qsvt_pair(b.x, b.y, C, SP, SN, ONE, NEG2);
        u64 r67 = qsvt_pair(b.z, b.w, C, SP, SN, ONE, NEG2);

        float4 o1, o2;
        unpk2(r01, o1.x, o1.y);
        unpk2(r23, o1.z, o1.w);
        unpk2(r45, o2.x, o2.y);
        unpk2(r67, o2.z, o2.w);
        *reinterpret_cast<float4*>(out + base)     = o1;
        *reinterpret_cast<float4*>(out + base + 4) = o2;
    } else {
        // tail (not hit for 4096*4096, kept for safety)
        for (long long i = base; i < n; i++) {
            u64 r = qsvt_pair(xin[i], 0.0f, C, SP, SN, ONE, NEG2);
            float lo, hi;
            unpk2(r, lo, hi);
            out[i] = lo;
        }
    }
}

extern "C" void kernel_launch(void* const* d_in, const int* in_sizes, int n_in,
                              void* d_out, int out_size) {
    const float* x   = (const float*)d_in[0];
    // d_in[1] = theta: provably dead (diagonal phase, does not affect <Z>)
    const float* phi = (const float*)d_in[2];
    float* out = (float*)d_out;

    qsvt_setup<<<1, 32>>>(phi);

    int n = out_size;
    long long threads = ((long long)n + 7) / 8;
    int blocks = (int)((threads + 255) / 256);
    qsvt_main<<<blocks, 256>>>(x, out, n);
}